// round 8
// baseline (speedup 1.0000x reference)
#include <cuda_runtime.h>
#include <cstdint>

#define E_ 16
#define T_ 256
#define H_ 2048
#define I_ 1024

// 16 MB intermediate: h[e,t,i] = silu(gate)*up (fp32)
__device__ float g_hbuf[E_ * T_ * I_];

__device__ __forceinline__ uint32_t f2tf32(float x) {
    uint32_t r;
    asm("cvt.rna.tf32.f32 %0, %1;" : "=r"(r) : "f"(x));
    return r;
}

// D += A(16x8 row) * B(8x8 col), tf32 inputs, f32 accum.
__device__ __forceinline__ void mma8(float c[4], const uint32_t a[4], const uint32_t b[2]) {
    asm volatile(
        "mma.sync.aligned.m16n8k8.row.col.f32.tf32.tf32.f32 "
        "{%0,%1,%2,%3}, {%4,%5,%6,%7}, {%8,%9}, {%0,%1,%2,%3};"
        : "+f"(c[0]), "+f"(c[1]), "+f"(c[2]), "+f"(c[3])
        : "r"(a[0]), "r"(a[1]), "r"(a[2]), "r"(a[3]), "r"(b[0]), "r"(b[1]));
}

#define PADK 36   // 32 k-floats padded to 36 (144B rows, 16B aligned)

// stage sizes in 32-bit words
#define GU_STAGE ((64 + 128 + 128) * PADK)   // 11520 words = 46080 B
#define DN_STAGE ((128 + 128) * PADK)        //  9216 words = 36864 B

// ---------------------------------------------------------------------------
// Kernel A: fused gate+up.  grid=(I/128, T/64, E), block=512.
// Block tile: 64(M) x 128(N) x 32(K). 16 warps (2m x 8n), warp tile 32x16 (x2 gemm).
// Double-buffered SMEM, 1 __syncthreads per K-chunk.
// ---------------------------------------------------------------------------
__global__ __launch_bounds__(512)
void moe_gateup_mma(const float* __restrict__ x,
                    const float* __restrict__ wg,
                    const float* __restrict__ wu)
{
    extern __shared__ char smraw[];
    uint32_t* sm = (uint32_t*)smraw;

    const int tid  = threadIdx.x;
    const int e    = blockIdx.z;
    const int row0 = blockIdx.y * 64;    // token block
    const int col0 = blockIdx.x * 128;   // I block
    const int w    = tid >> 5, lane = tid & 31;
    const int gid  = lane >> 2, tg = lane & 3;
    const int m0   = (w >> 3) * 32;      // 0 or 32
    const int n0   = (w & 7) * 16;       // 0..112

    const float4* x4 = (const float4*)(x + (size_t)row0 * H_);
    const float4* g4 = (const float4*)(wg + ((size_t)e * I_ + col0) * H_);
    const float4* u4 = (const float4*)(wu + ((size_t)e * I_ + col0) * H_);

    const int ra  = tid >> 3, fa = tid & 7;           // A: 1 float4/thread
    const int rw0 = tid >> 3, rw1 = (tid + 512) >> 3; // W: 2 float4/thread
    const int fw  = tid & 7;

    // per-thread staging offsets (relative to stage base)
    const int oA  = ra  * PADK + fa * 4;
    const int oG0 = 64 * PADK + rw0 * PADK + fw * 4;
    const int oG1 = 64 * PADK + rw1 * PADK + fw * 4;
    const int oU0 = 192 * PADK + rw0 * PADK + fw * 4;
    const int oU1 = 192 * PADK + rw1 * PADK + fw * 4;

    float accg[2][2][4] = {};
    float accu[2][2][4] = {};

    float4 pA, pG0, pG1, pU0, pU1;
    pA  = x4[(size_t)ra  * 512 + fa];
    pG0 = g4[(size_t)rw0 * 512 + fw];
    pG1 = g4[(size_t)rw1 * 512 + fw];
    pU0 = u4[(size_t)rw0 * 512 + fw];
    pU1 = u4[(size_t)rw1 * 512 + fw];

    const int NCH = H_ / 32;   // 64
    for (int it = 0; it < NCH; ++it) {
        uint32_t* buf = sm + (it & 1) * GU_STAGE;

        // stage chunk it (tf32 convert)
        {
            uint32_t* d = buf + oA;
            d[0]=f2tf32(pA.x); d[1]=f2tf32(pA.y); d[2]=f2tf32(pA.z); d[3]=f2tf32(pA.w);
            d = buf + oG0;
            d[0]=f2tf32(pG0.x); d[1]=f2tf32(pG0.y); d[2]=f2tf32(pG0.z); d[3]=f2tf32(pG0.w);
            d = buf + oG1;
            d[0]=f2tf32(pG1.x); d[1]=f2tf32(pG1.y); d[2]=f2tf32(pG1.z); d[3]=f2tf32(pG1.w);
            d = buf + oU0;
            d[0]=f2tf32(pU0.x); d[1]=f2tf32(pU0.y); d[2]=f2tf32(pU0.z); d[3]=f2tf32(pU0.w);
            d = buf + oU1;
            d[0]=f2tf32(pU1.x); d[1]=f2tf32(pU1.y); d[2]=f2tf32(pU1.z); d[3]=f2tf32(pU1.w);
        }
        __syncthreads();

        if (it + 1 < NCH) {   // prefetch next chunk; latency hidden by compute
            const int o = (it + 1) * 8;
            pA  = x4[(size_t)ra  * 512 + o + fa];
            pG0 = g4[(size_t)rw0 * 512 + o + fw];
            pG1 = g4[(size_t)rw1 * 512 + o + fw];
            pU0 = u4[(size_t)rw0 * 512 + o + fw];
            pU1 = u4[(size_t)rw1 * 512 + o + fw];
        }

        const uint32_t* As = buf;
        const uint32_t* Gs = buf + 64 * PADK;
        const uint32_t* Us = buf + 192 * PADK;
#pragma unroll
        for (int k = 0; k < 4; ++k) {
            const int k0 = k * 8;
            uint32_t a[2][4];
#pragma unroll
            for (int mt = 0; mt < 2; ++mt) {
                const int rb = (m0 + mt * 16 + gid) * PADK + k0 + tg;
                a[mt][0] = As[rb];
                a[mt][1] = As[rb + 8 * PADK];
                a[mt][2] = As[rb + 4];
                a[mt][3] = As[rb + 8 * PADK + 4];
            }
#pragma unroll
            for (int nt = 0; nt < 2; ++nt) {
                const int nb = (n0 + nt * 8 + gid) * PADK + k0 + tg;
                uint32_t bg[2] = { Gs[nb], Gs[nb + 4] };
                uint32_t bu[2] = { Us[nb], Us[nb + 4] };
                mma8(accg[0][nt], a[0], bg);
                mma8(accg[1][nt], a[1], bg);
                mma8(accu[0][nt], a[0], bu);
                mma8(accu[1][nt], a[1], bu);
            }
        }
        // no second sync: next iteration writes the other buffer
    }

    // epilogue: h = silu(g) * u
#pragma unroll
    for (int mt = 0; mt < 2; ++mt)
#pragma unroll
        for (int nt = 0; nt < 2; ++nt) {
            const int c = col0 + n0 + nt * 8 + tg * 2;
#pragma unroll
            for (int hh = 0; hh < 2; ++hh) {
                const int r = row0 + m0 + mt * 16 + gid + hh * 8;
                float g0 = accg[mt][nt][hh * 2 + 0], g1 = accg[mt][nt][hh * 2 + 1];
                float u0 = accu[mt][nt][hh * 2 + 0], u1 = accu[mt][nt][hh * 2 + 1];
                float2 v;
                v.x = g0 / (1.0f + __expf(-g0)) * u0;
                v.y = g1 / (1.0f + __expf(-g1)) * u1;
                *(float2*)(g_hbuf + ((size_t)e * T_ + r) * I_ + c) = v;
            }
        }
}

// ---------------------------------------------------------------------------
// Kernel B: down projection.  grid=(H/128, T/128, E), block=512.
// Block tile: 128 x 128 x 32. 16 warps (4m x 4n), warp tile 32x32.
// Double-buffered SMEM, 1 __syncthreads per K-chunk.
// ---------------------------------------------------------------------------
__global__ __launch_bounds__(512)
void moe_down_mma(const float* __restrict__ wd,
                  float* __restrict__ out)
{
    extern __shared__ char smraw[];
    uint32_t* sm = (uint32_t*)smraw;

    const int tid  = threadIdx.x;
    const int e    = blockIdx.z;
    const int row0 = blockIdx.y * 128;
    const int col0 = blockIdx.x * 128;   // H block
    const int w    = tid >> 5, lane = tid & 31;
    const int gid  = lane >> 2, tg = lane & 3;
    const int m0   = (w >> 2) * 32;
    const int n0   = (w & 3) * 32;

    const float4* h4 = (const float4*)(g_hbuf + ((size_t)e * T_ + row0) * I_);
    const float4* b4 = (const float4*)(wd + ((size_t)e * H_ + col0) * I_);

    const int r0 = tid >> 3, r1 = (tid + 512) >> 3;
    const int ff = tid & 7;

    const int oA0 = r0 * PADK + ff * 4;
    const int oA1 = r1 * PADK + ff * 4;
    const int oB0 = 128 * PADK + r0 * PADK + ff * 4;
    const int oB1 = 128 * PADK + r1 * PADK + ff * 4;

    float acc[2][4][4] = {};

    float4 pA0, pA1, pB0, pB1;
    pA0 = h4[(size_t)r0 * 256 + ff];
    pA1 = h4[(size_t)r1 * 256 + ff];
    pB0 = b4[(size_t)r0 * 256 + ff];
    pB1 = b4[(size_t)r1 * 256 + ff];

    const int NCH = I_ / 32;   // 32
    for (int it = 0; it < NCH; ++it) {
        uint32_t* buf = sm + (it & 1) * DN_STAGE;
        {
            uint32_t* d = buf + oA0;
            d[0]=f2tf32(pA0.x); d[1]=f2tf32(pA0.y); d[2]=f2tf32(pA0.z); d[3]=f2tf32(pA0.w);
            d = buf + oA1;
            d[0]=f2tf32(pA1.x); d[1]=f2tf32(pA1.y); d[2]=f2tf32(pA1.z); d[3]=f2tf32(pA1.w);
            d = buf + oB0;
            d[0]=f2tf32(pB0.x); d[1]=f2tf32(pB0.y); d[2]=f2tf32(pB0.z); d[3]=f2tf32(pB0.w);
            d = buf + oB1;
            d[0]=f2tf32(pB1.x); d[1]=f2tf32(pB1.y); d[2]=f2tf32(pB1.z); d[3]=f2tf32(pB1.w);
        }
        __syncthreads();

        if (it + 1 < NCH) {
            const int o = (it + 1) * 8;
            pA0 = h4[(size_t)r0 * 256 + o + ff];
            pA1 = h4[(size_t)r1 * 256 + o + ff];
            pB0 = b4[(size_t)r0 * 256 + o + ff];
            pB1 = b4[(size_t)r1 * 256 + o + ff];
        }

        const uint32_t* As = buf;
        const uint32_t* Bs = buf + 128 * PADK;
#pragma unroll
        for (int k = 0; k < 4; ++k) {
            const int k0 = k * 8;
            uint32_t a[2][4];
#pragma unroll
            for (int mt = 0; mt < 2; ++mt) {
                const int rb = (m0 + mt * 16 + gid) * PADK + k0 + tg;
                a[mt][0] = As[rb];
                a[mt][1] = As[rb + 8 * PADK];
                a[mt][2] = As[rb + 4];
                a[mt][3] = As[rb + 8 * PADK + 4];
            }
#pragma unroll
            for (int nt = 0; nt < 4; ++nt) {
                const int nb = (n0 + nt * 8 + gid) * PADK + k0 + tg;
                uint32_t bb[2] = { Bs[nb], Bs[nb + 4] };
                mma8(acc[0][nt], a[0], bb);
                mma8(acc[1][nt], a[1], bb);
            }
        }
    }

#pragma unroll
    for (int mt = 0; mt < 2; ++mt)
#pragma unroll
        for (int nt = 0; nt < 4; ++nt) {
            const int c = col0 + n0 + nt * 8 + tg * 2;
#pragma unroll
            for (int hh = 0; hh < 2; ++hh) {
                const int r = row0 + m0 + mt * 16 + gid + hh * 8;
                float2 v;
                v.x = acc[mt][nt][hh * 2 + 0];
                v.y = acc[mt][nt][hh * 2 + 1];
                *(float2*)(out + ((size_t)e * T_ + r) * H_ + c) = v;
            }
        }
}

// ---------------------------------------------------------------------------
extern "C" void kernel_launch(void* const* d_in, const int* in_sizes, int n_in,
                              void* d_out, int out_size)
{
    const float* x  = (const float*)d_in[0];   // [T, H]
    const float* wg = (const float*)d_in[1];   // [E, I, H]
    const float* wu = (const float*)d_in[2];   // [E, I, H]
    const float* wd = (const float*)d_in[3];   // [E, H, I]
    float* out = (float*)d_out;                // [E*T, H]

    const int SM1 = 2 * GU_STAGE * 4;   // 92160 B
    const int SM2 = 2 * DN_STAGE * 4;   // 73728 B
    cudaFuncSetAttribute(moe_gateup_mma, cudaFuncAttributeMaxDynamicSharedMemorySize, SM1);
    cudaFuncSetAttribute(moe_down_mma,   cudaFuncAttributeMaxDynamicSharedMemorySize, SM2);

    dim3 gridA(I_ / 128, T_ / 64, E_);    // (8, 4, 16)
    dim3 gridB(H_ / 128, T_ / 128, E_);   // (16, 2, 16)

    moe_gateup_mma<<<gridA, 512, SM1>>>(x, wg, wu);
    moe_down_mma<<<gridB, 512, SM2>>>(wd, out);
}

// round 10
// speedup vs baseline: 1.2215x; 1.2215x over previous
#include <cuda_runtime.h>
#include <cstdint>

#define E_ 16
#define T_ 256
#define H_ 2048
#define I_ 1024

// 16 MB intermediate: h[e,t,i] = silu(gate)*up (fp32)
__device__ float g_hbuf[E_ * T_ * I_];

__device__ __forceinline__ uint32_t f2tf32(float x) {
    uint32_t r;
    asm("cvt.rna.tf32.f32 %0, %1;" : "=r"(r) : "f"(x));
    return r;
}

// D += A(16x8 row) * B(8x8 col), tf32 inputs, f32 accum.
__device__ __forceinline__ void mma8(float c[4], const uint32_t a[4], const uint32_t b[2]) {
    asm volatile(
        "mma.sync.aligned.m16n8k8.row.col.f32.tf32.tf32.f32 "
        "{%0,%1,%2,%3}, {%4,%5,%6,%7}, {%8,%9}, {%0,%1,%2,%3};"
        : "+f"(c[0]), "+f"(c[1]), "+f"(c[2]), "+f"(c[3])
        : "r"(a[0]), "r"(a[1]), "r"(a[2]), "r"(a[3]), "r"(b[0]), "r"(b[1]));
}

#define PADK 36   // 32 k-floats padded to 36 words (conflict-free scalar LDS)

// ---------------------------------------------------------------------------
// Kernel A: fused gate+up.  grid=(I/64, T/64, E), block=256, 2 CTAs/SM.
// Block tile: 64(M) x 64(N) x 32(K). 8 warps (2m x 4n), warp tile 32x16 (x2 gemm).
// Single-buffer SMEM, STS; sync; LDG-prefetch; compute; sync  (round-5 scheme).
// ---------------------------------------------------------------------------
__global__ __launch_bounds__(256, 2)
void moe_gateup_mma(const float* __restrict__ x,
                    const float* __restrict__ wg,
                    const float* __restrict__ wu)
{
    extern __shared__ char smraw[];
    uint32_t* As = (uint32_t*)smraw;        // 64 x 36
    uint32_t* Gs = As + 64 * PADK;          // 64 x 36
    uint32_t* Us = Gs + 64 * PADK;          // 64 x 36

    const int tid  = threadIdx.x;
    const int e    = blockIdx.z;
    const int row0 = blockIdx.y * 64;    // token block
    const int col0 = blockIdx.x * 64;    // I block
    const int w    = tid >> 5, lane = tid & 31;
    const int gid  = lane >> 2, tg = lane & 3;
    const int m0   = (w >> 2) * 32;      // 0 or 32
    const int n0   = (w & 3) * 16;       // 0..48

    const float4* x4 = (const float4*)(x + (size_t)row0 * H_);
    const float4* g4 = (const float4*)(wg + ((size_t)e * I_ + col0) * H_);
    const float4* u4 = (const float4*)(wu + ((size_t)e * I_ + col0) * H_);

    // staging map: 64 rows x 8 float4 = 512 slots; 256 threads -> 2 each
    const int r0 = tid >> 3, r1 = r0 + 32;
    const int f  = tid & 7;

    const int oA0 = r0 * PADK + f * 4, oA1 = r1 * PADK + f * 4;

    float accg[2][2][4] = {};
    float accu[2][2][4] = {};

    float4 pA0, pA1, pG0, pG1, pU0, pU1;
    pA0 = x4[(size_t)r0 * 512 + f];
    pA1 = x4[(size_t)r1 * 512 + f];
    pG0 = g4[(size_t)r0 * 512 + f];
    pG1 = g4[(size_t)r1 * 512 + f];
    pU0 = u4[(size_t)r0 * 512 + f];
    pU1 = u4[(size_t)r1 * 512 + f];

    const int NCH = H_ / 32;   // 64
    for (int it = 0; it < NCH; ++it) {
        // stage chunk it (tf32 convert)
        {
            uint32_t* d = As + oA0;
            d[0]=f2tf32(pA0.x); d[1]=f2tf32(pA0.y); d[2]=f2tf32(pA0.z); d[3]=f2tf32(pA0.w);
            d = As + oA1;
            d[0]=f2tf32(pA1.x); d[1]=f2tf32(pA1.y); d[2]=f2tf32(pA1.z); d[3]=f2tf32(pA1.w);
            d = Gs + oA0;
            d[0]=f2tf32(pG0.x); d[1]=f2tf32(pG0.y); d[2]=f2tf32(pG0.z); d[3]=f2tf32(pG0.w);
            d = Gs + oA1;
            d[0]=f2tf32(pG1.x); d[1]=f2tf32(pG1.y); d[2]=f2tf32(pG1.z); d[3]=f2tf32(pG1.w);
            d = Us + oA0;
            d[0]=f2tf32(pU0.x); d[1]=f2tf32(pU0.y); d[2]=f2tf32(pU0.z); d[3]=f2tf32(pU0.w);
            d = Us + oA1;
            d[0]=f2tf32(pU1.x); d[1]=f2tf32(pU1.y); d[2]=f2tf32(pU1.z); d[3]=f2tf32(pU1.w);
        }
        __syncthreads();

        if (it + 1 < NCH) {   // prefetch next chunk; latency hidden by compute
            const int o = (it + 1) * 8;
            pA0 = x4[(size_t)r0 * 512 + o + f];
            pA1 = x4[(size_t)r1 * 512 + o + f];
            pG0 = g4[(size_t)r0 * 512 + o + f];
            pG1 = g4[(size_t)r1 * 512 + o + f];
            pU0 = u4[(size_t)r0 * 512 + o + f];
            pU1 = u4[(size_t)r1 * 512 + o + f];
        }

#pragma unroll
        for (int k = 0; k < 4; ++k) {
            const int k0 = k * 8;
            uint32_t a[2][4];
#pragma unroll
            for (int mt = 0; mt < 2; ++mt) {
                const int rb = (m0 + mt * 16 + gid) * PADK + k0 + tg;
                a[mt][0] = As[rb];
                a[mt][1] = As[rb + 8 * PADK];
                a[mt][2] = As[rb + 4];
                a[mt][3] = As[rb + 8 * PADK + 4];
            }
#pragma unroll
            for (int nt = 0; nt < 2; ++nt) {
                const int nb = (n0 + nt * 8 + gid) * PADK + k0 + tg;
                uint32_t bg[2] = { Gs[nb], Gs[nb + 4] };
                uint32_t bu[2] = { Us[nb], Us[nb + 4] };
                mma8(accg[0][nt], a[0], bg);
                mma8(accg[1][nt], a[1], bg);
                mma8(accu[0][nt], a[0], bu);
                mma8(accu[1][nt], a[1], bu);
            }
        }
        __syncthreads();
    }

    // epilogue: h = silu(g) * u
#pragma unroll
    for (int mt = 0; mt < 2; ++mt)
#pragma unroll
        for (int nt = 0; nt < 2; ++nt) {
            const int c = col0 + n0 + nt * 8 + tg * 2;
#pragma unroll
            for (int hh = 0; hh < 2; ++hh) {
                const int r = row0 + m0 + mt * 16 + gid + hh * 8;
                float g0 = accg[mt][nt][hh * 2 + 0], g1 = accg[mt][nt][hh * 2 + 1];
                float u0 = accu[mt][nt][hh * 2 + 0], u1 = accu[mt][nt][hh * 2 + 1];
                float2 v;
                v.x = g0 / (1.0f + __expf(-g0)) * u0;
                v.y = g1 / (1.0f + __expf(-g1)) * u1;
                *(float2*)(g_hbuf + ((size_t)e * T_ + r) * I_ + c) = v;
            }
        }
}

// ---------------------------------------------------------------------------
// Kernel B: down projection.  grid=(H/64, T/128, E), block=256, 2 CTAs/SM.
// Block tile: 128(M) x 64(N) x 32(K). 8 warps (4m x 2n), warp tile 32x32.
// Single-buffer SMEM, two syncs per iter.
// ---------------------------------------------------------------------------
__global__ __launch_bounds__(256, 2)
void moe_down_mma(const float* __restrict__ wd,
                  float* __restrict__ out)
{
    extern __shared__ char smraw[];
    uint32_t* As = (uint32_t*)smraw;         // 128 x 36
    uint32_t* Bs = As + 128 * PADK;          // 64 x 36

    const int tid  = threadIdx.x;
    const int e    = blockIdx.z;
    const int row0 = blockIdx.y * 128;
    const int col0 = blockIdx.x * 64;    // H block
    const int w    = tid >> 5, lane = tid & 31;
    const int gid  = lane >> 2, tg = lane & 3;
    const int m0   = (w >> 1) * 32;      // 0..96
    const int n0   = (w & 1) * 32;       // 0 or 32

    const float4* h4 = (const float4*)(g_hbuf + ((size_t)e * T_ + row0) * I_);
    const float4* b4 = (const float4*)(wd + ((size_t)e * H_ + col0) * I_);

    // A: 128 rows x 8 f4 = 1024 slots -> 4/thread; B: 64 x 8 = 512 -> 2/thread
    const int r0 = tid >> 3, f = tid & 7;

    float acc[2][4][4] = {};

    float4 pA[4], pB[2];
#pragma unroll
    for (int j = 0; j < 4; ++j) pA[j] = h4[(size_t)(r0 + 32 * j) * 256 + f];
#pragma unroll
    for (int j = 0; j < 2; ++j) pB[j] = b4[(size_t)(r0 + 32 * j) * 256 + f];

    const int NCH = I_ / 32;   // 32
    for (int it = 0; it < NCH; ++it) {
        {
#pragma unroll
            for (int j = 0; j < 4; ++j) {
                uint32_t* d = As + (r0 + 32 * j) * PADK + f * 4;
                d[0]=f2tf32(pA[j].x); d[1]=f2tf32(pA[j].y);
                d[2]=f2tf32(pA[j].z); d[3]=f2tf32(pA[j].w);
            }
#pragma unroll
            for (int j = 0; j < 2; ++j) {
                uint32_t* d = Bs + (r0 + 32 * j) * PADK + f * 4;
                d[0]=f2tf32(pB[j].x); d[1]=f2tf32(pB[j].y);
                d[2]=f2tf32(pB[j].z); d[3]=f2tf32(pB[j].w);
            }
        }
        __syncthreads();

        if (it + 1 < NCH) {
            const int o = (it + 1) * 8;
#pragma unroll
            for (int j = 0; j < 4; ++j) pA[j] = h4[(size_t)(r0 + 32 * j) * 256 + o + f];
#pragma unroll
            for (int j = 0; j < 2; ++j) pB[j] = b4[(size_t)(r0 + 32 * j) * 256 + o + f];
        }

#pragma unroll
        for (int k = 0; k < 4; ++k) {
            const int k0 = k * 8;
            uint32_t a[2][4];
#pragma unroll
            for (int mt = 0; mt < 2; ++mt) {
                const int rb = (m0 + mt * 16 + gid) * PADK + k0 + tg;
                a[mt][0] = As[rb];
                a[mt][1] = As[rb + 8 * PADK];
                a[mt][2] = As[rb + 4];
                a[mt][3] = As[rb + 8 * PADK + 4];
            }
#pragma unroll
            for (int nt = 0; nt < 4; ++nt) {
                const int nb = (n0 + nt * 8 + gid) * PADK + k0 + tg;
                uint32_t bb[2] = { Bs[nb], Bs[nb + 4] };
                mma8(acc[0][nt], a[0], bb);
                mma8(acc[1][nt], a[1], bb);
            }
        }
        __syncthreads();
    }

#pragma unroll
    for (int mt = 0; mt < 2; ++mt)
#pragma unroll
        for (int nt = 0; nt < 4; ++nt) {
            const int c = col0 + n0 + nt * 8 + tg * 2;
#pragma unroll
            for (int hh = 0; hh < 2; ++hh) {
                const int r = row0 + m0 + mt * 16 + gid + hh * 8;
                float2 v;
                v.x = acc[mt][nt][hh * 2 + 0];
                v.y = acc[mt][nt][hh * 2 + 1];
                *(float2*)(out + ((size_t)e * T_ + r) * H_ + c) = v;
            }
        }
}

// ---------------------------------------------------------------------------
extern "C" void kernel_launch(void* const* d_in, const int* in_sizes, int n_in,
                              void* d_out, int out_size)
{
    const float* x  = (const float*)d_in[0];   // [T, H]
    const float* wg = (const float*)d_in[1];   // [E, I, H]
    const float* wu = (const float*)d_in[2];   // [E, I, H]
    const float* wd = (const float*)d_in[3];   // [E, H, I]
    float* out = (float*)d_out;                // [E*T, H]

    const int SM1 = (64 + 64 + 64) * PADK * 4;   // 27648 B
    const int SM2 = (128 + 64) * PADK * 4;       // 27648 B
    cudaFuncSetAttribute(moe_gateup_mma, cudaFuncAttributeMaxDynamicSharedMemorySize, SM1);
    cudaFuncSetAttribute(moe_down_mma,   cudaFuncAttributeMaxDynamicSharedMemorySize, SM2);

    dim3 gridA(I_ / 64, T_ / 64, E_);     // (16, 4, 16)
    dim3 gridB(H_ / 64, T_ / 128, E_);    // (32, 2, 16)

    moe_gateup_mma<<<gridA, 256, SM1>>>(x, wg, wu);
    moe_down_mma<<<gridB, 256, SM2>>>(wd, out);
}

// round 12
// speedup vs baseline: 1.3701x; 1.1217x over previous
#include <cuda_runtime.h>
#include <cuda_fp16.h>
#include <cstdint>

#define E_ 16
#define T_ 256
#define H_ 2048
#define I_ 1024

// 16 MB intermediate: h[e,t,i] = silu(gate)*up (fp32)
__device__ float g_hbuf[E_ * T_ * I_];

__device__ __forceinline__ uint32_t packh2(float lo, float hi) {
    __half2 h = __floats2half2_rn(lo, hi);
    return *reinterpret_cast<uint32_t*>(&h);
}

// D += A(16x16 row) * B(16x8 col), fp16 inputs, f32 accum.
__device__ __forceinline__ void mma16(float c[4], const uint32_t a[4], const uint32_t b[2]) {
    asm volatile(
        "mma.sync.aligned.m16n8k16.row.col.f32.f16.f16.f32 "
        "{%0,%1,%2,%3}, {%4,%5,%6,%7}, {%8,%9}, {%0,%1,%2,%3};"
        : "+f"(c[0]), "+f"(c[1]), "+f"(c[2]), "+f"(c[3])
        : "r"(a[0]), "r"(a[1]), "r"(a[2]), "r"(a[3]), "r"(b[0]), "r"(b[1]));
}

#define ROWW 20   // 32 halves = 16 words + 4 pad (fragment LDS conflict-free)

__device__ __forceinline__ void sts_row8(uint32_t* base, int off,
                                         const float4& lo, const float4& hi) {
    uint4 v;
    v.x = packh2(lo.x, lo.y);
    v.y = packh2(lo.z, lo.w);
    v.z = packh2(hi.x, hi.y);
    v.w = packh2(hi.z, hi.w);
    *reinterpret_cast<uint4*>(base + off) = v;
}

// ---------------------------------------------------------------------------
// Kernel A: fused gate+up.  grid=(I/64, T/64, E), block=256, 2 CTAs/SM.
// Block tile: 64(M) x 64(N) x 32(K). 8 warps (2m x 4n), warp tile 32x16 (x2 gemm).
// fp16 operands in SMEM, f32 accum.  STS; sync; prefetch; compute; sync.
// ---------------------------------------------------------------------------
__global__ __launch_bounds__(256, 2)
void moe_gateup_mma(const float* __restrict__ x,
                    const float* __restrict__ wg,
                    const float* __restrict__ wu)
{
    extern __shared__ char smraw[];
    uint32_t* As = (uint32_t*)smraw;        // 64 x 20 words
    uint32_t* Gs = As + 64 * ROWW;
    uint32_t* Us = Gs + 64 * ROWW;

    const int tid  = threadIdx.x;
    const int e    = blockIdx.z;
    const int row0 = blockIdx.y * 64;    // token block
    const int col0 = blockIdx.x * 64;    // I block
    const int w    = tid >> 5, lane = tid & 31;
    const int gid  = lane >> 2, tg = lane & 3;
    const int m0   = (w >> 2) * 32;      // 0 or 32
    const int n0   = (w & 3) * 16;       // 0..48

    const float4* x4 = (const float4*)(x + (size_t)row0 * H_);
    const float4* g4 = (const float4*)(wg + ((size_t)e * I_ + col0) * H_);
    const float4* u4 = (const float4*)(wu + ((size_t)e * I_ + col0) * H_);

    // staging: thread -> row=tid>>2 (0..63), fq=tid&3 covers k 8*fq..8*fq+7
    const int srow = tid >> 2, fq = tid & 3;
    const int oS = srow * ROWW + fq * 4;                 // word offset (16B aligned)
    const size_t gOff = (size_t)srow * 512 + fq * 2;     // float4 index, row stride 512

    float accg[2][2][4] = {};
    float accu[2][2][4] = {};

    float4 pA0, pA1, pG0, pG1, pU0, pU1;
    pA0 = x4[gOff];     pA1 = x4[gOff + 1];
    pG0 = g4[gOff];     pG1 = g4[gOff + 1];
    pU0 = u4[gOff];     pU1 = u4[gOff + 1];

    const int NCH = H_ / 32;   // 64
    for (int it = 0; it < NCH; ++it) {
        sts_row8(As, oS, pA0, pA1);
        sts_row8(Gs, oS, pG0, pG1);
        sts_row8(Us, oS, pU0, pU1);
        __syncthreads();

        if (it + 1 < NCH) {   // prefetch next chunk; latency hidden by compute
            const size_t o = gOff + (size_t)(it + 1) * 8;
            pA0 = x4[o]; pA1 = x4[o + 1];
            pG0 = g4[o]; pG1 = g4[o + 1];
            pU0 = u4[o]; pU1 = u4[o + 1];
        }

#pragma unroll
        for (int ks = 0; ks < 2; ++ks) {       // two k16 steps per 32-K chunk
            const int k0 = ks * 8;
            uint32_t a[2][4];
#pragma unroll
            for (int mt = 0; mt < 2; ++mt) {
                const int rb = (m0 + mt * 16 + gid) * ROWW + k0 + tg;
                a[mt][0] = As[rb];
                a[mt][1] = As[rb + 8 * ROWW];
                a[mt][2] = As[rb + 4];
                a[mt][3] = As[rb + 8 * ROWW + 4];
            }
#pragma unroll
            for (int nt = 0; nt < 2; ++nt) {
                const int nb = (n0 + nt * 8 + gid) * ROWW + k0 + tg;
                uint32_t bg[2] = { Gs[nb], Gs[nb + 4] };
                uint32_t bu[2] = { Us[nb], Us[nb + 4] };
                mma16(accg[0][nt], a[0], bg);
                mma16(accg[1][nt], a[1], bg);
                mma16(accu[0][nt], a[0], bu);
                mma16(accu[1][nt], a[1], bu);
            }
        }
        __syncthreads();
    }

    // epilogue: h = silu(g) * u
#pragma unroll
    for (int mt = 0; mt < 2; ++mt)
#pragma unroll
        for (int nt = 0; nt < 2; ++nt) {
            const int c = col0 + n0 + nt * 8 + tg * 2;
#pragma unroll
            for (int hh = 0; hh < 2; ++hh) {
                const int r = row0 + m0 + mt * 16 + gid + hh * 8;
                float g0 = accg[mt][nt][hh * 2 + 0], g1 = accg[mt][nt][hh * 2 + 1];
                float u0 = accu[mt][nt][hh * 2 + 0], u1 = accu[mt][nt][hh * 2 + 1];
                float2 v;
                v.x = g0 / (1.0f + __expf(-g0)) * u0;
                v.y = g1 / (1.0f + __expf(-g1)) * u1;
                *(float2*)(g_hbuf + ((size_t)e * T_ + r) * I_ + c) = v;
            }
        }
}

// ---------------------------------------------------------------------------
// Kernel B: down projection.  grid=(H/64, T/128, E), block=256, 2 CTAs/SM.
// Block tile: 128(M) x 64(N) x 32(K). 8 warps (4m x 2n), warp tile 32x32.
// ---------------------------------------------------------------------------
__global__ __launch_bounds__(256, 2)
void moe_down_mma(const float* __restrict__ wd,
                  float* __restrict__ out)
{
    extern __shared__ char smraw[];
    uint32_t* As = (uint32_t*)smraw;         // 128 x 20 words
    uint32_t* Bs = As + 128 * ROWW;          // 64 x 20

    const int tid  = threadIdx.x;
    const int e    = blockIdx.z;
    const int row0 = blockIdx.y * 128;
    const int col0 = blockIdx.x * 64;    // H block
    const int w    = tid >> 5, lane = tid & 31;
    const int gid  = lane >> 2, tg = lane & 3;
    const int m0   = (w >> 1) * 32;      // 0..96
    const int n0   = (w & 1) * 32;       // 0 or 32

    const float4* h4 = (const float4*)(g_hbuf + ((size_t)e * T_ + row0) * I_);
    const float4* b4 = (const float4*)(wd + ((size_t)e * H_ + col0) * I_);

    const int srow = tid >> 2, fq = tid & 3;
    const int oA0 = srow * ROWW + fq * 4;
    const int oA1 = (srow + 64) * ROWW + fq * 4;
    const int oB  = srow * ROWW + fq * 4;
    const size_t gA0 = (size_t)srow * 256 + fq * 2;          // I row = 256 f4
    const size_t gA1 = (size_t)(srow + 64) * 256 + fq * 2;
    const size_t gB  = (size_t)srow * 256 + fq * 2;

    float acc[2][4][4] = {};

    float4 pA0a, pA0b, pA1a, pA1b, pBa, pBb;
    pA0a = h4[gA0];     pA0b = h4[gA0 + 1];
    pA1a = h4[gA1];     pA1b = h4[gA1 + 1];
    pBa  = b4[gB];      pBb  = b4[gB + 1];

    const int NCH = I_ / 32;   // 32
    for (int it = 0; it < NCH; ++it) {
        sts_row8(As, oA0, pA0a, pA0b);
        sts_row8(As, oA1, pA1a, pA1b);
        sts_row8(Bs, oB,  pBa,  pBb);
        __syncthreads();

        if (it + 1 < NCH) {
            const size_t o = (size_t)(it + 1) * 8;
            pA0a = h4[gA0 + o]; pA0b = h4[gA0 + o + 1];
            pA1a = h4[gA1 + o]; pA1b = h4[gA1 + o + 1];
            pBa  = b4[gB + o];  pBb  = b4[gB + o + 1];
        }

#pragma unroll
        for (int ks = 0; ks < 2; ++ks) {
            const int k0 = ks * 8;
            uint32_t a[2][4];
#pragma unroll
            for (int mt = 0; mt < 2; ++mt) {
                const int rb = (m0 + mt * 16 + gid) * ROWW + k0 + tg;
                a[mt][0] = As[rb];
                a[mt][1] = As[rb + 8 * ROWW];
                a[mt][2] = As[rb + 4];
                a[mt][3] = As[rb + 8 * ROWW + 4];
            }
#pragma unroll
            for (int nt = 0; nt < 4; ++nt) {
                const int nb = (n0 + nt * 8 + gid) * ROWW + k0 + tg;
                uint32_t bb[2] = { Bs[nb], Bs[nb + 4] };
                mma16(acc[0][nt], a[0], bb);
                mma16(acc[1][nt], a[1], bb);
            }
        }
        __syncthreads();
    }

#pragma unroll
    for (int mt = 0; mt < 2; ++mt)
#pragma unroll
        for (int nt = 0; nt < 4; ++nt) {
            const int c = col0 + n0 + nt * 8 + tg * 2;
#pragma unroll
            for (int hh = 0; hh < 2; ++hh) {
                const int r = row0 + m0 + mt * 16 + gid + hh * 8;
                float2 v;
                v.x = acc[mt][nt][hh * 2 + 0];
                v.y = acc[mt][nt][hh * 2 + 1];
                *(float2*)(out + ((size_t)e * T_ + r) * H_ + c) = v;
            }
        }
}

// ---------------------------------------------------------------------------
extern "C" void kernel_launch(void* const* d_in, const int* in_sizes, int n_in,
                              void* d_out, int out_size)
{
    const float* x  = (const float*)d_in[0];   // [T, H]
    const float* wg = (const float*)d_in[1];   // [E, I, H]
    const float* wu = (const float*)d_in[2];   // [E, I, H]
    const float* wd = (const float*)d_in[3];   // [E, H, I]
    float* out = (float*)d_out;                // [E*T, H]

    const int SM1 = 3 * 64 * ROWW * 4;          // 15360 B
    const int SM2 = (128 + 64) * ROWW * 4;      // 15360 B
    cudaFuncSetAttribute(moe_gateup_mma, cudaFuncAttributeMaxDynamicSharedMemorySize, SM1);
    cudaFuncSetAttribute(moe_down_mma,   cudaFuncAttributeMaxDynamicSharedMemorySize, SM2);

    dim3 gridA(I_ / 64, T_ / 64, E_);     // (16, 4, 16)
    dim3 gridB(H_ / 64, T_ / 128, E_);    // (32, 2, 16)

    moe_gateup_mma<<<gridA, 256, SM1>>>(x, wg, wu);
    moe_down_mma<<<gridB, 256, SM2>>>(wd, out);
}

// round 14
// speedup vs baseline: 2.1276x; 1.5529x over previous
#include <cuda_runtime.h>
#include <cuda_fp16.h>
#include <cstdint>

#define E_ 16
#define T_ 256
#define H_ 2048
#define I_ 1024

// fp16 copy of x (1 MB), fp16 intermediate h (8 MB)
__device__ __half g_xh[T_ * H_];
__device__ __half g_hbuf_h[E_ * T_ * I_];

__device__ __forceinline__ uint32_t packh2(float lo, float hi) {
    __half2 h = __floats2half2_rn(lo, hi);
    return *reinterpret_cast<uint32_t*>(&h);
}

// D += A(16x16 row) * B(16x8 col), fp16 inputs, f32 accum.
__device__ __forceinline__ void mma16(float c[4], const uint32_t a[4], const uint32_t b[2]) {
    asm volatile(
        "mma.sync.aligned.m16n8k16.row.col.f32.f16.f16.f32 "
        "{%0,%1,%2,%3}, {%4,%5,%6,%7}, {%8,%9}, {%0,%1,%2,%3};"
        : "+f"(c[0]), "+f"(c[1]), "+f"(c[2]), "+f"(c[3])
        : "r"(a[0]), "r"(a[1]), "r"(a[2]), "r"(a[3]), "r"(b[0]), "r"(b[1]));
}

#define ROWW 20   // 32 halves = 16 words + 4 pad; fragment LDS + ldrow conflict-free

__device__ __forceinline__ uint32_t smem_u32(const void* p) {
    uint32_t a;
    asm("{ .reg .u64 t; cvta.to.shared.u64 t, %1; cvt.u32.u64 %0, t; }" : "=r"(a) : "l"(p));
    return a;
}
__device__ __forceinline__ void cpasync16(uint32_t saddr, const void* gaddr) {
    asm volatile("cp.async.cg.shared.global [%0], [%1], 16;" :: "r"(saddr), "l"(gaddr) : "memory");
}
#define CP_COMMIT() asm volatile("cp.async.commit_group;" ::: "memory")
#define CP_WAIT(n)  asm volatile("cp.async.wait_group %0;" :: "n"(n) : "memory")

__device__ __forceinline__ void sts_row8(uint32_t* base, int off,
                                         const float4& lo, const float4& hi) {
    uint4 v;
    v.x = packh2(lo.x, lo.y);
    v.y = packh2(lo.z, lo.w);
    v.z = packh2(hi.x, hi.y);
    v.w = packh2(hi.z, hi.w);
    *reinterpret_cast<uint4*>(base + off) = v;
}

// ---------------------------------------------------------------------------
// cvt_x: x fp32 -> g_xh fp16.  65536 threads, 8 elems each.
// ---------------------------------------------------------------------------
__global__ void cvt_x_kernel(const float* __restrict__ x)
{
    int t = blockIdx.x * blockDim.x + threadIdx.x;   // 0..65535
    const float4* x4 = (const float4*)x;
    float4 a = x4[2 * t], b = x4[2 * t + 1];
    uint4 v;
    v.x = packh2(a.x, a.y); v.y = packh2(a.z, a.w);
    v.z = packh2(b.x, b.y); v.w = packh2(b.z, b.w);
    *reinterpret_cast<uint4*>(g_xh + 8 * t) = v;
}

// ---------------------------------------------------------------------------
// Kernel A: fused gate+up.  grid=(I/64, T/128, E), block=256, 2 CTAs/SM.
// Block tile: 128(M) x 64(N) x 32(K). 8 warps (2m x 4n), warp tile 64x16 (x2 gemm).
// A (x fp16) via cp.async double-buffer; G/U fp32 LDG->cvt->STS single-buffer.
// ---------------------------------------------------------------------------
__global__ __launch_bounds__(256, 2)
void moe_gateup_mma(const float* __restrict__ wg,
                    const float* __restrict__ wu)
{
    extern __shared__ char smraw[];
    uint32_t* A0 = (uint32_t*)smraw;        // 128 x 20 words
    uint32_t* A1 = A0 + 128 * ROWW;
    uint32_t* Gs = A1 + 128 * ROWW;         // 64 x 20
    uint32_t* Us = Gs + 64 * ROWW;          // 64 x 20

    const int tid  = threadIdx.x;
    const int e    = blockIdx.z;
    const int row0 = blockIdx.y * 128;   // token block
    const int col0 = blockIdx.x * 64;    // I block
    const int w    = tid >> 5, lane = tid & 31;
    const int gid  = lane >> 2, tg = lane & 3;
    const int m0   = (w >> 2) * 64;      // 0 or 64
    const int n0   = (w & 3) * 16;       // 0..48

    // staging ids: srow covers one 8-half slot per round
    const int srow = tid >> 2, fq = tid & 3;

    // A source (fp16) rows row0+srow, row0+srow+64
    const __half* xA = g_xh + (size_t)row0 * H_;
    const __half* gA0 = xA + (size_t)srow * H_ + fq * 8;
    const __half* gA1 = xA + (size_t)(srow + 64) * H_ + fq * 8;
    const uint32_t sA0w = (uint32_t)(srow * ROWW + fq * 4);
    const uint32_t sA1w = (uint32_t)((srow + 64) * ROWW + fq * 4);
    const uint32_t a0b = smem_u32(A0), a1b = smem_u32(A1);

    // G/U source (fp32), 64 rows
    const float4* g4 = (const float4*)(wg + ((size_t)e * I_ + col0) * H_);
    const float4* u4 = (const float4*)(wu + ((size_t)e * I_ + col0) * H_);
    const size_t gW = (size_t)srow * 512 + fq * 2;
    const int oS = srow * ROWW + fq * 4;

    float accg[4][2][4] = {};
    float accu[4][2][4] = {};

    // prologue: A(0) via cp.async, G/U(0) via LDG
    cpasync16(a0b + sA0w * 4, gA0);
    cpasync16(a0b + sA1w * 4, gA1);
    CP_COMMIT();
    float4 pG0 = g4[gW], pG1 = g4[gW + 1];
    float4 pU0 = u4[gW], pU1 = u4[gW + 1];

    const int NCH = H_ / 32;   // 64
    for (int it = 0; it < NCH; ++it) {
        sts_row8(Gs, oS, pG0, pG1);
        sts_row8(Us, oS, pU0, pU1);
        if (it + 1 < NCH) {
            const uint32_t nb = ((it + 1) & 1) ? a1b : a0b;
            const int ko = (it + 1) * 32;    // halves
            cpasync16(nb + sA0w * 4, gA0 + ko);
            cpasync16(nb + sA1w * 4, gA1 + ko);
            CP_COMMIT();
            CP_WAIT(1);
        } else {
            CP_WAIT(0);
        }
        __syncthreads();

        if (it + 1 < NCH) {
            const size_t o = gW + (size_t)(it + 1) * 8;
            pG0 = g4[o]; pG1 = g4[o + 1];
            pU0 = u4[o]; pU1 = u4[o + 1];
        }

        const uint32_t* Ab = (it & 1) ? A1 : A0;
#pragma unroll
        for (int ks = 0; ks < 2; ++ks) {
            const int k0 = ks * 8;
            uint32_t a[4][4];
#pragma unroll
            for (int mt = 0; mt < 4; ++mt) {
                const int rb = (m0 + mt * 16 + gid) * ROWW + k0 + tg;
                a[mt][0] = Ab[rb];
                a[mt][1] = Ab[rb + 8 * ROWW];
                a[mt][2] = Ab[rb + 4];
                a[mt][3] = Ab[rb + 8 * ROWW + 4];
            }
#pragma unroll
            for (int nt = 0; nt < 2; ++nt) {
                const int nb = (n0 + nt * 8 + gid) * ROWW + k0 + tg;
                uint32_t bg[2] = { Gs[nb], Gs[nb + 4] };
                uint32_t bu[2] = { Us[nb], Us[nb + 4] };
#pragma unroll
                for (int mt = 0; mt < 4; ++mt) {
                    mma16(accg[mt][nt], a[mt], bg);
                    mma16(accu[mt][nt], a[mt], bu);
                }
            }
        }
        __syncthreads();
    }

    // epilogue: h = silu(g) * u -> fp16
#pragma unroll
    for (int mt = 0; mt < 4; ++mt)
#pragma unroll
        for (int nt = 0; nt < 2; ++nt) {
            const int c = col0 + n0 + nt * 8 + tg * 2;
#pragma unroll
            for (int hh = 0; hh < 2; ++hh) {
                const int r = row0 + m0 + mt * 16 + gid + hh * 8;
                float g0 = accg[mt][nt][hh * 2 + 0], g1 = accg[mt][nt][hh * 2 + 1];
                float u0 = accu[mt][nt][hh * 2 + 0], u1 = accu[mt][nt][hh * 2 + 1];
                float h0 = g0 / (1.0f + __expf(-g0)) * u0;
                float h1 = g1 / (1.0f + __expf(-g1)) * u1;
                *reinterpret_cast<uint32_t*>(
                    g_hbuf_h + ((size_t)e * T_ + r) * I_ + c) = packh2(h0, h1);
            }
        }
}

// ---------------------------------------------------------------------------
// Kernel B: down projection.  grid=(H/128, T/128, E), block=256, 2 CTAs/SM.
// Block tile: 128(M) x 128(N) x 32(K). 8 warps (2m x 4n), warp tile 64x32.
// A (h fp16) via cp.async double-buffer; B fp32 LDG->cvt->STS single-buffer.
// ---------------------------------------------------------------------------
__global__ __launch_bounds__(256, 2)
void moe_down_mma(const float* __restrict__ wd,
                  float* __restrict__ out)
{
    extern __shared__ char smraw[];
    uint32_t* A0 = (uint32_t*)smraw;        // 128 x 20 words
    uint32_t* A1 = A0 + 128 * ROWW;
    uint32_t* Bs = A1 + 128 * ROWW;         // 128 x 20

    const int tid  = threadIdx.x;
    const int e    = blockIdx.z;
    const int row0 = blockIdx.y * 128;
    const int col0 = blockIdx.x * 128;   // H block
    const int w    = tid >> 5, lane = tid & 31;
    const int gid  = lane >> 2, tg = lane & 3;
    const int m0   = (w >> 2) * 64;      // 0 or 64
    const int n0   = (w & 3) * 32;       // 0..96

    const int srow = tid >> 2, fq = tid & 3;

    // A source: h fp16 rows row0+srow, +64
    const __half* hA = g_hbuf_h + ((size_t)e * T_ + row0) * I_;
    const __half* gA0 = hA + (size_t)srow * I_ + fq * 8;
    const __half* gA1 = hA + (size_t)(srow + 64) * I_ + fq * 8;
    const uint32_t sA0w = (uint32_t)(srow * ROWW + fq * 4);
    const uint32_t sA1w = (uint32_t)((srow + 64) * ROWW + fq * 4);
    const uint32_t a0b = smem_u32(A0), a1b = smem_u32(A1);

    // B source: wd fp32, 128 rows, two rounds (srow, srow+64)
    const float4* b4 = (const float4*)(wd + ((size_t)e * H_ + col0) * I_);
    const size_t gB0 = (size_t)srow * 256 + fq * 2;
    const size_t gB1 = (size_t)(srow + 64) * 256 + fq * 2;
    const int oB0 = srow * ROWW + fq * 4;
    const int oB1 = (srow + 64) * ROWW + fq * 4;

    float acc[4][4][4] = {};

    cpasync16(a0b + sA0w * 4, gA0);
    cpasync16(a0b + sA1w * 4, gA1);
    CP_COMMIT();
    float4 pB0a = b4[gB0], pB0b = b4[gB0 + 1];
    float4 pB1a = b4[gB1], pB1b = b4[gB1 + 1];

    const int NCH = I_ / 32;   // 32
    for (int it = 0; it < NCH; ++it) {
        sts_row8(Bs, oB0, pB0a, pB0b);
        sts_row8(Bs, oB1, pB1a, pB1b);
        if (it + 1 < NCH) {
            const uint32_t nb = ((it + 1) & 1) ? a1b : a0b;
            const int ko = (it + 1) * 32;
            cpasync16(nb + sA0w * 4, gA0 + ko);
            cpasync16(nb + sA1w * 4, gA1 + ko);
            CP_COMMIT();
            CP_WAIT(1);
        } else {
            CP_WAIT(0);
        }
        __syncthreads();

        if (it + 1 < NCH) {
            const size_t o = (size_t)(it + 1) * 8;
            pB0a = b4[gB0 + o]; pB0b = b4[gB0 + o + 1];
            pB1a = b4[gB1 + o]; pB1b = b4[gB1 + o + 1];
        }

        const uint32_t* Ab = (it & 1) ? A1 : A0;
#pragma unroll
        for (int ks = 0; ks < 2; ++ks) {
            const int k0 = ks * 8;
            uint32_t a[4][4];
#pragma unroll
            for (int mt = 0; mt < 4; ++mt) {
                const int rb = (m0 + mt * 16 + gid) * ROWW + k0 + tg;
                a[mt][0] = Ab[rb];
                a[mt][1] = Ab[rb + 8 * ROWW];
                a[mt][2] = Ab[rb + 4];
                a[mt][3] = Ab[rb + 8 * ROWW + 4];
            }
#pragma unroll
            for (int nt = 0; nt < 4; ++nt) {
                const int nb = (n0 + nt * 8 + gid) * ROWW + k0 + tg;
                uint32_t bb[2] = { Bs[nb], Bs[nb + 4] };
#pragma unroll
                for (int mt = 0; mt < 4; ++mt)
                    mma16(acc[mt][nt], a[mt], bb);
            }
        }
        __syncthreads();
    }

#pragma unroll
    for (int mt = 0; mt < 4; ++mt)
#pragma unroll
        for (int nt = 0; nt < 4; ++nt) {
            const int c = col0 + n0 + nt * 8 + tg * 2;
#pragma unroll
            for (int hh = 0; hh < 2; ++hh) {
                const int r = row0 + m0 + mt * 16 + gid + hh * 8;
                float2 v;
                v.x = acc[mt][nt][hh * 2 + 0];
                v.y = acc[mt][nt][hh * 2 + 1];
                *(float2*)(out + ((size_t)e * T_ + r) * H_ + c) = v;
            }
        }
}

// ---------------------------------------------------------------------------
extern "C" void kernel_launch(void* const* d_in, const int* in_sizes, int n_in,
                              void* d_out, int out_size)
{
    const float* x  = (const float*)d_in[0];   // [T, H]
    const float* wg = (const float*)d_in[1];   // [E, I, H]
    const float* wu = (const float*)d_in[2];   // [E, I, H]
    const float* wd = (const float*)d_in[3];   // [E, H, I]
    float* out = (float*)d_out;                // [E*T, H]

    const int SM1 = (2 * 128 + 64 + 64) * ROWW * 4;   // 30720 B
    const int SM2 = (2 * 128 + 128) * ROWW * 4;       // 30720 B

    cvt_x_kernel<<<T_ * H_ / 8 / 256, 256>>>(x);
    dim3 gridA(I_ / 64, T_ / 128, E_);     // (16, 2, 16)
    dim3 gridB(H_ / 128, T_ / 128, E_);    // (16, 2, 16)
    moe_gateup_mma<<<gridA, 256, SM1>>>(wg, wu);
    moe_down_mma<<<gridB, 256, SM2>>>(wd, out);
}

// round 15
// speedup vs baseline: 2.2431x; 1.0543x over previous
#include <cuda_runtime.h>
#include <cuda_fp16.h>
#include <cstdint>

#define E_ 16
#define T_ 256
#define H_ 2048
#define I_ 1024

// fp16 copy of x (1 MB), fp16 intermediate h (8 MB)
__device__ __half g_xh[T_ * H_];
__device__ __half g_hbuf_h[E_ * T_ * I_];

__device__ __forceinline__ uint32_t packh2(float lo, float hi) {
    __half2 h = __floats2half2_rn(lo, hi);
    return *reinterpret_cast<uint32_t*>(&h);
}

// D += A(16x16 row) * B(16x8 col), fp16 inputs, f32 accum.
__device__ __forceinline__ void mma16(float c[4], const uint32_t a[4], const uint32_t b[2]) {
    asm volatile(
        "mma.sync.aligned.m16n8k16.row.col.f32.f16.f16.f32 "
        "{%0,%1,%2,%3}, {%4,%5,%6,%7}, {%8,%9}, {%0,%1,%2,%3};"
        : "+f"(c[0]), "+f"(c[1]), "+f"(c[2]), "+f"(c[3])
        : "r"(a[0]), "r"(a[1]), "r"(a[2]), "r"(a[3]), "r"(b[0]), "r"(b[1]));
}

#define ROWW 20   // 32 halves = 16 words + 4 pad; fragment LDS + ldrow conflict-free

__device__ __forceinline__ uint32_t smem_u32(const void* p) {
    uint32_t a;
    asm("{ .reg .u64 t; cvta.to.shared.u64 t, %1; cvt.u32.u64 %0, t; }" : "=r"(a) : "l"(p));
    return a;
}
__device__ __forceinline__ void cpasync16(uint32_t saddr, const void* gaddr) {
    asm volatile("cp.async.cg.shared.global [%0], [%1], 16;" :: "r"(saddr), "l"(gaddr) : "memory");
}
#define CP_COMMIT() asm volatile("cp.async.commit_group;" ::: "memory")
#define CP_WAIT(n)  asm volatile("cp.async.wait_group %0;" :: "n"(n) : "memory")

__device__ __forceinline__ void sts_row8(uint32_t* base, int off,
                                         const float4& lo, const float4& hi) {
    uint4 v;
    v.x = packh2(lo.x, lo.y);
    v.y = packh2(lo.z, lo.w);
    v.z = packh2(hi.x, hi.y);
    v.w = packh2(hi.z, hi.w);
    *reinterpret_cast<uint4*>(base + off) = v;
}

// ---------------------------------------------------------------------------
// cvt_x: x fp32 -> g_xh fp16.  65536 threads, 8 elems each.
// ---------------------------------------------------------------------------
__global__ void cvt_x_kernel(const float* __restrict__ x)
{
    int t = blockIdx.x * blockDim.x + threadIdx.x;   // 0..65535
    const float4* x4 = (const float4*)x;
    float4 a = x4[2 * t], b = x4[2 * t + 1];
    uint4 v;
    v.x = packh2(a.x, a.y); v.y = packh2(a.z, a.w);
    v.z = packh2(b.x, b.y); v.w = packh2(b.z, b.w);
    *reinterpret_cast<uint4*>(g_xh + 8 * t) = v;
}

// ---------------------------------------------------------------------------
// Kernel A: fused gate+up.  grid=(I/64, T/128, E), block=256, 2 CTAs/SM.
// Block tile: 128(M) x 64(N) x 32(K). 8 warps (2m x 4n), warp tile 64x16 (x2 gemm).
// A (x fp16) via cp.async double-buffer; G/U fp32 LDG->cvt->STS single-buffer.
// ---------------------------------------------------------------------------
__global__ __launch_bounds__(256, 2)
void moe_gateup_mma(const float* __restrict__ wg,
                    const float* __restrict__ wu)
{
    extern __shared__ char smraw[];
    uint32_t* A0 = (uint32_t*)smraw;        // 128 x 20 words
    uint32_t* A1 = A0 + 128 * ROWW;
    uint32_t* Gs = A1 + 128 * ROWW;         // 64 x 20
    uint32_t* Us = Gs + 64 * ROWW;          // 64 x 20

    const int tid  = threadIdx.x;
    const int e    = blockIdx.z;
    const int row0 = blockIdx.y * 128;   // token block
    const int col0 = blockIdx.x * 64;    // I block
    const int w    = tid >> 5, lane = tid & 31;
    const int gid  = lane >> 2, tg = lane & 3;
    const int m0   = (w >> 2) * 64;      // 0 or 64
    const int n0   = (w & 3) * 16;       // 0..48

    // staging ids: srow covers one 8-half slot per round
    const int srow = tid >> 2, fq = tid & 3;

    // A source (fp16) rows row0+srow, row0+srow+64
    const __half* xA = g_xh + (size_t)row0 * H_;
    const __half* gA0 = xA + (size_t)srow * H_ + fq * 8;
    const __half* gA1 = xA + (size_t)(srow + 64) * H_ + fq * 8;
    const uint32_t sA0w = (uint32_t)(srow * ROWW + fq * 4);
    const uint32_t sA1w = (uint32_t)((srow + 64) * ROWW + fq * 4);
    const uint32_t a0b = smem_u32(A0), a1b = smem_u32(A1);

    // G/U source (fp32), 64 rows
    const float4* g4 = (const float4*)(wg + ((size_t)e * I_ + col0) * H_);
    const float4* u4 = (const float4*)(wu + ((size_t)e * I_ + col0) * H_);
    const size_t gW = (size_t)srow * 512 + fq * 2;
    const int oS = srow * ROWW + fq * 4;

    float accg[4][2][4] = {};
    float accu[4][2][4] = {};

    // prologue: A(0) via cp.async, G/U(0) via LDG
    cpasync16(a0b + sA0w * 4, gA0);
    cpasync16(a0b + sA1w * 4, gA1);
    CP_COMMIT();
    float4 pG0 = g4[gW], pG1 = g4[gW + 1];
    float4 pU0 = u4[gW], pU1 = u4[gW + 1];

    const int NCH = H_ / 32;   // 64
    for (int it = 0; it < NCH; ++it) {
        sts_row8(Gs, oS, pG0, pG1);
        sts_row8(Us, oS, pU0, pU1);
        if (it + 1 < NCH) {
            const uint32_t nb = ((it + 1) & 1) ? a1b : a0b;
            const int ko = (it + 1) * 32;    // halves
            cpasync16(nb + sA0w * 4, gA0 + ko);
            cpasync16(nb + sA1w * 4, gA1 + ko);
            CP_COMMIT();
            CP_WAIT(1);
        } else {
            CP_WAIT(0);
        }
        __syncthreads();

        if (it + 1 < NCH) {
            const size_t o = gW + (size_t)(it + 1) * 8;
            pG0 = g4[o]; pG1 = g4[o + 1];
            pU0 = u4[o]; pU1 = u4[o + 1];
        }

        const uint32_t* Ab = (it & 1) ? A1 : A0;
#pragma unroll
        for (int ks = 0; ks < 2; ++ks) {
            const int k0 = ks * 8;
            uint32_t a[4][4];
#pragma unroll
            for (int mt = 0; mt < 4; ++mt) {
                const int rb = (m0 + mt * 16 + gid) * ROWW + k0 + tg;
                a[mt][0] = Ab[rb];
                a[mt][1] = Ab[rb + 8 * ROWW];
                a[mt][2] = Ab[rb + 4];
                a[mt][3] = Ab[rb + 8 * ROWW + 4];
            }
#pragma unroll
            for (int nt = 0; nt < 2; ++nt) {
                const int nb = (n0 + nt * 8 + gid) * ROWW + k0 + tg;
                uint32_t bg[2] = { Gs[nb], Gs[nb + 4] };
                uint32_t bu[2] = { Us[nb], Us[nb + 4] };
#pragma unroll
                for (int mt = 0; mt < 4; ++mt) {
                    mma16(accg[mt][nt], a[mt], bg);
                    mma16(accu[mt][nt], a[mt], bu);
                }
            }
        }
        __syncthreads();
    }

    // epilogue: h = silu(g) * u -> fp16
#pragma unroll
    for (int mt = 0; mt < 4; ++mt)
#pragma unroll
        for (int nt = 0; nt < 2; ++nt) {
            const int c = col0 + n0 + nt * 8 + tg * 2;
#pragma unroll
            for (int hh = 0; hh < 2; ++hh) {
                const int r = row0 + m0 + mt * 16 + gid + hh * 8;
                float g0 = accg[mt][nt][hh * 2 + 0], g1 = accg[mt][nt][hh * 2 + 1];
                float u0 = accu[mt][nt][hh * 2 + 0], u1 = accu[mt][nt][hh * 2 + 1];
                float h0 = g0 / (1.0f + __expf(-g0)) * u0;
                float h1 = g1 / (1.0f + __expf(-g1)) * u1;
                *reinterpret_cast<uint32_t*>(
                    g_hbuf_h + ((size_t)e * T_ + r) * I_ + c) = packh2(h0, h1);
            }
        }
}

// ---------------------------------------------------------------------------
// Kernel B: down projection.  grid=(H/128, T/128, E), block=256, 2 CTAs/SM.
// Block tile: 128(M) x 128(N) x 32(K). 8 warps (2m x 4n), warp tile 64x32.
// A (h fp16) via cp.async double-buffer; B fp32 LDG->cvt->STS single-buffer.
// ---------------------------------------------------------------------------
__global__ __launch_bounds__(256, 2)
void moe_down_mma(const float* __restrict__ wd,
                  float* __restrict__ out)
{
    extern __shared__ char smraw[];
    uint32_t* A0 = (uint32_t*)smraw;        // 128 x 20 words
    uint32_t* A1 = A0 + 128 * ROWW;
    uint32_t* Bs = A1 + 128 * ROWW;         // 128 x 20

    const int tid  = threadIdx.x;
    const int e    = blockIdx.z;
    const int row0 = blockIdx.y * 128;
    const int col0 = blockIdx.x * 128;   // H block
    const int w    = tid >> 5, lane = tid & 31;
    const int gid  = lane >> 2, tg = lane & 3;
    const int m0   = (w >> 2) * 64;      // 0 or 64
    const int n0   = (w & 3) * 32;       // 0..96

    const int srow = tid >> 2, fq = tid & 3;

    // A source: h fp16 rows row0+srow, +64
    const __half* hA = g_hbuf_h + ((size_t)e * T_ + row0) * I_;
    const __half* gA0 = hA + (size_t)srow * I_ + fq * 8;
    const __half* gA1 = hA + (size_t)(srow + 64) * I_ + fq * 8;
    const uint32_t sA0w = (uint32_t)(srow * ROWW + fq * 4);
    const uint32_t sA1w = (uint32_t)((srow + 64) * ROWW + fq * 4);
    const uint32_t a0b = smem_u32(A0), a1b = smem_u32(A1);

    // B source: wd fp32, 128 rows, two rounds (srow, srow+64)
    const float4* b4 = (const float4*)(wd + ((size_t)e * H_ + col0) * I_);
    const size_t gB0 = (size_t)srow * 256 + fq * 2;
    const size_t gB1 = (size_t)(srow + 64) * 256 + fq * 2;
    const int oB0 = srow * ROWW + fq * 4;
    const int oB1 = (srow + 64) * ROWW + fq * 4;

    float acc[4][4][4] = {};

    cpasync16(a0b + sA0w * 4, gA0);
    cpasync16(a0b + sA1w * 4, gA1);
    CP_COMMIT();
    float4 pB0a = b4[gB0], pB0b = b4[gB0 + 1];
    float4 pB1a = b4[gB1], pB1b = b4[gB1 + 1];

    const int NCH = I_ / 32;   // 32
    for (int it = 0; it < NCH; ++it) {
        sts_row8(Bs, oB0, pB0a, pB0b);
        sts_row8(Bs, oB1, pB1a, pB1b);
        if (it + 1 < NCH) {
            const uint32_t nb = ((it + 1) & 1) ? a1b : a0b;
            const int ko = (it + 1) * 32;
            cpasync16(nb + sA0w * 4, gA0 + ko);
            cpasync16(nb + sA1w * 4, gA1 + ko);
            CP_COMMIT();
            CP_WAIT(1);
        } else {
            CP_WAIT(0);
        }
        __syncthreads();

        if (it + 1 < NCH) {
            const size_t o = (size_t)(it + 1) * 8;
            pB0a = b4[gB0 + o]; pB0b = b4[gB0 + o + 1];
            pB1a = b4[gB1 + o]; pB1b = b4[gB1 + o + 1];
        }

        const uint32_t* Ab = (it & 1) ? A1 : A0;
#pragma unroll
        for (int ks = 0; ks < 2; ++ks) {
            const int k0 = ks * 8;
            uint32_t a[4][4];
#pragma unroll
            for (int mt = 0; mt < 4; ++mt) {
                const int rb = (m0 + mt * 16 + gid) * ROWW + k0 + tg;
                a[mt][0] = Ab[rb];
                a[mt][1] = Ab[rb + 8 * ROWW];
                a[mt][2] = Ab[rb + 4];
                a[mt][3] = Ab[rb + 8 * ROWW + 4];
            }
#pragma unroll
            for (int nt = 0; nt < 4; ++nt) {
                const int nb = (n0 + nt * 8 + gid) * ROWW + k0 + tg;
                uint32_t bb[2] = { Bs[nb], Bs[nb + 4] };
#pragma unroll
                for (int mt = 0; mt < 4; ++mt)
                    mma16(acc[mt][nt], a[mt], bb);
            }
        }
        __syncthreads();
    }

#pragma unroll
    for (int mt = 0; mt < 4; ++mt)
#pragma unroll
        for (int nt = 0; nt < 4; ++nt) {
            const int c = col0 + n0 + nt * 8 + tg * 2;
#pragma unroll
            for (int hh = 0; hh < 2; ++hh) {
                const int r = row0 + m0 + mt * 16 + gid + hh * 8;
                float2 v;
                v.x = acc[mt][nt][hh * 2 + 0];
                v.y = acc[mt][nt][hh * 2 + 1];
                *(float2*)(out + ((size_t)e * T_ + r) * H_ + c) = v;
            }
        }
}

// ---------------------------------------------------------------------------
extern "C" void kernel_launch(void* const* d_in, const int* in_sizes, int n_in,
                              void* d_out, int out_size)
{
    const float* x  = (const float*)d_in[0];   // [T, H]
    const float* wg = (const float*)d_in[1];   // [E, I, H]
    const float* wu = (const float*)d_in[2];   // [E, I, H]
    const float* wd = (const float*)d_in[3];   // [E, H, I]
    float* out = (float*)d_out;                // [E*T, H]

    const int SM1 = (2 * 128 + 64 + 64) * ROWW * 4;   // 30720 B
    const int SM2 = (2 * 128 + 128) * ROWW * 4;       // 30720 B

    cvt_x_kernel<<<T_ * H_ / 8 / 256, 256>>>(x);
    dim3 gridA(I_ / 64, T_ / 128, E_);     // (16, 2, 16)
    dim3 gridB(H_ / 128, T_ / 128, E_);    // (16, 2, 16)
    moe_gateup_mma<<<gridA, 256, SM1>>>(wg, wu);
    moe_down_mma<<<gridB, 256, SM2>>>(wd, out);
}